// round 4
// baseline (speedup 1.0000x reference)
#include <cuda_runtime.h>
#include <math.h>

#define DTc 1e-4f
#define LN_EPS 1e-5f
#define B_ 16
#define S_ 4096
#define D_ 256
#define N_ 16
#define CHUNK 64
#define NCHUNK (S_/CHUNK)   // 64

// scratch (no cudaMalloc allowed)
__device__ float g_H[B_*S_*N_];          // 4 MB
__device__ float g_carry[B_*NCHUNK*N_];  // 64 KB

typedef unsigned long long ull;

__device__ __forceinline__ ull pack2(float v){          // (v, v)
    ull r;
    asm("mov.b64 %0, {%1, %1};" : "=l"(r) : "f"(v));
    return r;
}
__device__ __forceinline__ ull packab(float a, float b){
    ull r;
    asm("mov.b64 %0, {%1, %2};" : "=l"(r) : "f"(a), "f"(b));
    return r;
}
__device__ __forceinline__ void unpk(float& lo, float& hi, ull v){
    asm("mov.b64 {%0, %1}, %2;" : "=f"(lo), "=f"(hi) : "l"(v));
}
__device__ __forceinline__ void fma2(ull& d, ull a, ull b){
    asm("fma.rn.f32x2 %0, %1, %2, %0;" : "+l"(d) : "l"(a), "l"(b));
}
__device__ __forceinline__ ull mul2(ull a, ull b){
    ull r;
    asm("mul.rn.f32x2 %0, %1, %2;" : "=l"(r) : "l"(a), "l"(b));
    return r;
}

// ---------------------------------------------------------------------------
// K1: U = DT * x @ Bm^T for 128 rows (2 chunks), f32x2 register tile 2t x 4n
// (rows tt and tt+64), then per-chunk local scans. 256 thr, 3 blocks/SM.
// ---------------------------------------------------------------------------
__global__ void __launch_bounds__(256,3) k1(const float* __restrict__ x,
                                            const float* __restrict__ A,
                                            const float* __restrict__ Bm){
    extern __shared__ float sm[];
    float* sx  = sm;                       // 128*68 = 8704 words
    float* swT = sm + 128*68;              // [k][n] 256*16 = 4096 words
    float* su  = sm + 128*68 + 256*16;     // [t][n] pad 20: 128*20 words
    const int blk = blockIdx.x, b = blockIdx.y;
    const int tid = threadIdx.x;
    const int nt = tid & 3, tt = tid >> 2;     // tt 0..63

    // stage W transposed: swT[k][n] = DT * Bm[n][k]
    for (int i = tid; i < N_*D_; i += 256){
        int nn = i >> 8, k = i & 255;
        swT[k*16 + nn] = DTc * Bm[nn*D_ + k];
    }

    ull acc[2][2];   // [row(tt,tt+64)][n-pair]
    acc[0][0]=0; acc[0][1]=0; acc[1][0]=0; acc[1][1]=0;

    const float4* xg = (const float4*)(x + (size_t)(b*S_ + blk*128)*D_);

    #pragma unroll
    for (int kt = 0; kt < 4; kt++){
        __syncthreads();
        // stage x k-tile: 128 rows x 64 cols = 2048 float4
        #pragma unroll
        for (int j = 0; j < 8; j++){
            int i = tid + j*256;
            int t = i >> 4, q = i & 15;
            *(float4*)(sx + t*68 + q*4) = xg[t*64 + kt*16 + q];
        }
        __syncthreads();

        const float4* xr0 = (const float4*)(sx + tt*68);
        const float4* xr1 = (const float4*)(sx + (tt+64)*68);
        const float* wb = swT + kt*64*16 + nt*4;

        #pragma unroll
        for (int k4 = 0; k4 < 16; k4++){
            float4 xa = xr0[k4], xb = xr1[k4];
            ulonglong2 w0 = *(const ulonglong2*)(wb + (k4*4+0)*16);
            ulonglong2 w1 = *(const ulonglong2*)(wb + (k4*4+1)*16);
            ulonglong2 w2 = *(const ulonglong2*)(wb + (k4*4+2)*16);
            ulonglong2 w3 = *(const ulonglong2*)(wb + (k4*4+3)*16);
            ull s;
            s = pack2(xa.x); fma2(acc[0][0], s, w0.x); fma2(acc[0][1], s, w0.y);
            s = pack2(xa.y); fma2(acc[0][0], s, w1.x); fma2(acc[0][1], s, w1.y);
            s = pack2(xa.z); fma2(acc[0][0], s, w2.x); fma2(acc[0][1], s, w2.y);
            s = pack2(xa.w); fma2(acc[0][0], s, w3.x); fma2(acc[0][1], s, w3.y);
            s = pack2(xb.x); fma2(acc[1][0], s, w0.x); fma2(acc[1][1], s, w0.y);
            s = pack2(xb.y); fma2(acc[1][0], s, w1.x); fma2(acc[1][1], s, w1.y);
            s = pack2(xb.z); fma2(acc[1][0], s, w2.x); fma2(acc[1][1], s, w2.y);
            s = pack2(xb.w); fma2(acc[1][0], s, w3.x); fma2(acc[1][1], s, w3.y);
        }
    }
    __syncthreads();
    *(ulonglong2*)(su + tt*20 + nt*4)      = make_ulonglong2(acc[0][0], acc[0][1]);
    *(ulonglong2*)(su + (tt+64)*20 + nt*4) = make_ulonglong2(acc[1][0], acc[1][1]);
    __syncthreads();

    // local scans: 32 chains (2 chunks x 16 n), h0 = 0
    if (tid < 32){
        int n = tid & 15, cc = tid >> 4;
        float a = expf(-DTc*fabsf(A[n]));
        float h = 0.f;
        float* p = su + cc*64*20 + n;
        #pragma unroll 8
        for (int t = 0; t < CHUNK; t++){
            h = fmaf(a, h, p[t*20]);
            p[t*20] = h;
        }
    }
    __syncthreads();

    float* Hg = g_H + (size_t)(b*S_ + blk*128)*N_;
    #pragma unroll
    for (int j = 0; j < 8; j++){
        int i = tid + j*256;               // 2048 elems
        Hg[i] = su[(i>>4)*20 + (i&15)];
    }
}

// ---------------------------------------------------------------------------
// K2: carry recurrence across chunks. 256 threads = 16 b x 16 n.
// ---------------------------------------------------------------------------
__global__ void k2(const float* __restrict__ A){
    const int tid = threadIdx.x;
    const int b = tid >> 4, n = tid & 15;
    float a = expf(-DTc*fabsf(A[n]));
    float a2=a*a, a4=a2*a2, a8=a4*a4, a16=a8*a8, a32=a16*a16, a64=a32*a32;
    float v[NCHUNK];
    #pragma unroll
    for (int c = 0; c < NCHUNK; c++)
        v[c] = g_H[(size_t)(b*S_ + c*CHUNK + (CHUNK-1))*N_ + n];
    float carry = 0.f;
    #pragma unroll
    for (int c = 0; c < NCHUNK; c++){
        g_carry[b*(NCHUNK*N_) + c*N_ + n] = carry;
        carry = fmaf(a64, carry, v[c]);
    }
}

// ---------------------------------------------------------------------------
// K3: recombine carries, y = h @ Cm^T + x*Dv, clip, fused LayerNorm, store.
// 512 thr = 16 warps, warp owns 4 rows; f32x2 GEMM, lane owns d-pairs
// d = 2*lane + 64*j2.
// ---------------------------------------------------------------------------
__global__ void __launch_bounds__(512,2) k3(const float* __restrict__ x,
                                            const float* __restrict__ A,
                                            const float* __restrict__ Cm,
                                            const float* __restrict__ Dv,
                                            const float* __restrict__ gamma,
                                            const float* __restrict__ beta,
                                            float* __restrict__ out){
    __shared__ float sC[N_*260];      // [n][d] pad 260
    __shared__ float sh[N_*68];       // [n][t] pad 68
    __shared__ float sDv[D_], sg[D_], sb[D_];
    const int chunk = blockIdx.x, b = blockIdx.y;
    const int tid = threadIdx.x;

    for (int i = tid; i < D_*N_; i += 512){
        int d = i >> 4, n = i & 15;
        sC[n*260 + d] = Cm[i];        // Cm[d][n]
    }
    for (int i = tid; i < D_; i += 512){ sDv[i]=Dv[i]; sg[i]=gamma[i]; sb[i]=beta[i]; }
    {
        const float* Hg = g_H + (size_t)(b*S_ + chunk*CHUNK)*N_;
        #pragma unroll
        for (int j = 0; j < 2; j++){
            int i = tid + j*512;
            int t = i >> 4, n = i & 15;
            sh[n*68 + t] = Hg[i];
        }
    }
    __syncthreads();

    // carry fixup: 64 threads, 16-step segments
    if (tid < 64){
        int n = tid & 15, seg = tid >> 4;
        float absA = fabsf(A[n]);
        float a = expf(-DTc*absA);
        float p = g_carry[b*(NCHUNK*N_) + chunk*N_ + n] * expf(-DTc*absA*(float)(seg*16));
        float* row = sh + n*68 + seg*16;
        #pragma unroll
        for (int tl = 0; tl < 16; tl++){
            p *= a;
            row[tl] += p;
        }
    }
    __syncthreads();

    const int warp = tid >> 5, lane = tid & 31;
    const int t0 = warp * 4;
    const float* xr = x + (size_t)(b*S_ + chunk*CHUNK + t0)*D_;

    ull y2[4][4];
    #pragma unroll
    for (int r = 0; r < 4; r++)
        #pragma unroll
        for (int j2 = 0; j2 < 4; j2++){
            int d = 2*lane + 64*j2;
            float2 xv = *(const float2*)(xr + r*D_ + d);
            y2[r][j2] = mul2(packab(xv.x, xv.y), *(const ull*)(sDv + d));
        }

    #pragma unroll
    for (int n = 0; n < 16; n++){
        float4 h4 = *(const float4*)(sh + n*68 + t0);   // broadcast
        ull ha = pack2(h4.x), hb = pack2(h4.y), hc = pack2(h4.z), hd = pack2(h4.w);
        const float* sCn = sC + n*260;
        #pragma unroll
        for (int j2 = 0; j2 < 4; j2++){
            ull c2 = *(const ull*)(sCn + 2*lane + 64*j2);
            fma2(y2[0][j2], ha, c2);
            fma2(y2[1][j2], hb, c2);
            fma2(y2[2][j2], hc, c2);
            fma2(y2[3][j2], hd, c2);
        }
    }

    float* og = out + (size_t)(b*S_ + chunk*CHUNK + t0)*D_;
    #pragma unroll
    for (int r = 0; r < 4; r++){
        float yv[8];
        float s = 0.f, s2 = 0.f;
        #pragma unroll
        for (int j2 = 0; j2 < 4; j2++){
            float lo, hi;
            unpk(lo, hi, y2[r][j2]);
            lo = fminf(fmaxf(lo, -10.f), 10.f);
            hi = fminf(fmaxf(hi, -10.f), 10.f);
            yv[2*j2] = lo; yv[2*j2+1] = hi;
            s += lo + hi;
            s2 = fmaf(lo, lo, s2);
            s2 = fmaf(hi, hi, s2);
        }
        #pragma unroll
        for (int o = 16; o; o >>= 1){
            s  += __shfl_xor_sync(0xffffffffu, s,  o);
            s2 += __shfl_xor_sync(0xffffffffu, s2, o);
        }
        float mu   = s * (1.f/256.f);
        float var  = fmaf(s2, 1.f/256.f, -mu*mu);
        float rinv = rsqrtf(var + LN_EPS);
        #pragma unroll
        for (int j2 = 0; j2 < 4; j2++){
            int d = 2*lane + 64*j2;
            float2 o2;
            o2.x = fmaf((yv[2*j2]  -mu)*rinv, sg[d],   sb[d]);
            o2.y = fmaf((yv[2*j2+1]-mu)*rinv, sg[d+1], sb[d+1]);
            *(float2*)(og + r*D_ + d) = o2;
        }
    }
}

// ---------------------------------------------------------------------------
extern "C" void kernel_launch(void* const* d_in, const int* in_sizes, int n_in,
                              void* d_out, int out_size){
    const float* x     = (const float*)d_in[0];
    const float* A     = (const float*)d_in[1];
    const float* Bm    = (const float*)d_in[2];
    const float* Cm    = (const float*)d_in[3];
    const float* Dv    = (const float*)d_in[4];
    const float* gamma = (const float*)d_in[5];
    const float* beta  = (const float*)d_in[6];
    float* out = (float*)d_out;

    size_t smem1 = (size_t)(128*68 + 256*16 + 128*20) * sizeof(float); // 61440 B
    cudaFuncSetAttribute(k1, cudaFuncAttributeMaxDynamicSharedMemorySize, (int)smem1);

    dim3 grid1(S_/128, B_);     // 32 x 16 = 512 blocks
    dim3 grid3(NCHUNK, B_);     // 64 x 16
    k1<<<grid1, 256, smem1>>>(x, A, Bm);
    k2<<<1, 256>>>(A);
    k3<<<grid3, 512>>>(x, A, Cm, Dv, gamma, beta, out);
}

// round 5
// speedup vs baseline: 1.6845x; 1.6845x over previous
#include <cuda_runtime.h>
#include <math.h>

#define DTc 1e-4f
#define LN_EPS 1e-5f
#define B_ 16
#define S_ 4096
#define D_ 256
#define N_ 16
#define CHUNK 64
#define NCHUNK (S_/CHUNK)   // 64
#define PADX 36             // 32 k-cols + 4 pad

// scratch (no cudaMalloc allowed)
__device__ float g_H[B_*S_*N_];          // 4 MB
__device__ float g_carry[B_*NCHUNK*N_];  // 64 KB

__device__ __forceinline__ void fma4(float4& acc, float s, const float4& v){
    acc.x = fmaf(s, v.x, acc.x);
    acc.y = fmaf(s, v.y, acc.y);
    acc.z = fmaf(s, v.z, acc.z);
    acc.w = fmaf(s, v.w, acc.w);
}

__device__ __forceinline__ void cpa16(float* s, const float4* g){
    unsigned sa = (unsigned)__cvta_generic_to_shared(s);
    asm volatile("cp.async.ca.shared.global [%0], [%1], 16;" :: "r"(sa), "l"(g));
}

// ---------------------------------------------------------------------------
// K1: U = DT * x @ Bm^T for 256 rows (4 chunks). 256 thr; thread computes
// rows {tt, tt+64, tt+128, tt+192} x 4 n (conflict-free LDS), cp.async
// double-buffered 32-col k-tiles, then per-chunk local scans (h0=0).
// ---------------------------------------------------------------------------
__global__ void __launch_bounds__(256,2) k1(const float* __restrict__ x,
                                            const float* __restrict__ A,
                                            const float* __restrict__ Bm){
    extern __shared__ float sm[];
    float* sx0 = sm;                       // 256*36
    float* sx1 = sm + 256*PADX;            // 256*36
    float* swT = sm + 2*256*PADX;          // [k][n] 4096
    float* su  = swT + 4096;               // [row][n] pad 20: 5120
    const int blk = blockIdx.x, b = blockIdx.y;
    const int tid = threadIdx.x;
    const int nt = tid & 3, tt = tid >> 2; // tt 0..63

    // stage W transposed: swT[k][n] = DT * Bm[n][k]
    for (int i = tid; i < N_*D_; i += 256){
        int nn = i >> 8, k = i & 255;
        swT[k*16 + nn] = DTc * Bm[nn*D_ + k];
    }

    const float4* xg = (const float4*)(x + (size_t)(b*S_ + blk*256)*D_);

    float4 acc[4];
    #pragma unroll
    for (int i = 0; i < 4; i++) acc[i] = make_float4(0.f,0.f,0.f,0.f);

    // preload tile 0
    {
        #pragma unroll
        for (int j = 0; j < 8; j++){
            int i = tid + j*256;
            int t = i >> 3, q = i & 7;
            cpa16(sx0 + t*PADX + q*4, xg + (size_t)t*64 + q);
        }
        asm volatile("cp.async.commit_group;");
    }

    #pragma unroll
    for (int kt = 0; kt < 8; kt++){
        float* cur = (kt & 1) ? sx1 : sx0;
        float* nxt = (kt & 1) ? sx0 : sx1;
        if (kt < 7){
            #pragma unroll
            for (int j = 0; j < 8; j++){
                int i = tid + j*256;
                int t = i >> 3, q = i & 7;
                cpa16(nxt + t*PADX + q*4, xg + (size_t)t*64 + (kt+1)*8 + q);
            }
            asm volatile("cp.async.commit_group;");
            asm volatile("cp.async.wait_group 1;");
        } else {
            asm volatile("cp.async.wait_group 0;");
        }
        __syncthreads();

        const float4* xr0 = (const float4*)(cur + (tt      )*PADX);
        const float4* xr1 = (const float4*)(cur + (tt +  64)*PADX);
        const float4* xr2 = (const float4*)(cur + (tt + 128)*PADX);
        const float4* xr3 = (const float4*)(cur + (tt + 192)*PADX);
        const float* wb = swT + kt*32*16 + nt*4;

        #pragma unroll
        for (int k4 = 0; k4 < 8; k4++){
            float4 xa = xr0[k4], xb = xr1[k4], xc = xr2[k4], xd = xr3[k4];
            float4 w0 = *(const float4*)(wb + (k4*4+0)*16);
            float4 w1 = *(const float4*)(wb + (k4*4+1)*16);
            float4 w2 = *(const float4*)(wb + (k4*4+2)*16);
            float4 w3 = *(const float4*)(wb + (k4*4+3)*16);
            fma4(acc[0], xa.x, w0); fma4(acc[0], xa.y, w1); fma4(acc[0], xa.z, w2); fma4(acc[0], xa.w, w3);
            fma4(acc[1], xb.x, w0); fma4(acc[1], xb.y, w1); fma4(acc[1], xb.z, w2); fma4(acc[1], xb.w, w3);
            fma4(acc[2], xc.x, w0); fma4(acc[2], xc.y, w1); fma4(acc[2], xc.z, w2); fma4(acc[2], xc.w, w3);
            fma4(acc[3], xd.x, w0); fma4(acc[3], xd.y, w1); fma4(acc[3], xd.z, w2); fma4(acc[3], xd.w, w3);
        }
        __syncthreads();
    }

    *(float4*)(su + (tt      )*20 + nt*4) = acc[0];
    *(float4*)(su + (tt +  64)*20 + nt*4) = acc[1];
    *(float4*)(su + (tt + 128)*20 + nt*4) = acc[2];
    *(float4*)(su + (tt + 192)*20 + nt*4) = acc[3];
    __syncthreads();

    // local scans: 64 chains (4 chunks x 16 n), h0 = 0
    if (tid < 64){
        int n = tid & 15, cc = tid >> 4;
        float a = expf(-DTc*fabsf(A[n]));
        float h = 0.f;
        float* p = su + cc*64*20 + n;
        #pragma unroll 8
        for (int t = 0; t < CHUNK; t++){
            h = fmaf(a, h, p[t*20]);
            p[t*20] = h;
        }
    }
    __syncthreads();

    float* Hg = g_H + (size_t)(b*S_ + blk*256)*N_;
    #pragma unroll
    for (int j = 0; j < 16; j++){
        int i = tid + j*256;              // 4096 elems
        Hg[i] = su[(i>>4)*20 + (i&15)];
    }
}

// ---------------------------------------------------------------------------
// K2: carry recurrence across chunks. 256 threads = 16 b x 16 n.
// ---------------------------------------------------------------------------
__global__ void k2(const float* __restrict__ A){
    const int tid = threadIdx.x;
    const int b = tid >> 4, n = tid & 15;
    float a = expf(-DTc*fabsf(A[n]));
    float a2=a*a, a4=a2*a2, a8=a4*a4, a16=a8*a8, a32=a16*a16, a64=a32*a32;
    float v[NCHUNK];
    #pragma unroll
    for (int c = 0; c < NCHUNK; c++)
        v[c] = g_H[(size_t)(b*S_ + c*CHUNK + (CHUNK-1))*N_ + n];
    float carry = 0.f;
    #pragma unroll
    for (int c = 0; c < NCHUNK; c++){
        g_carry[b*(NCHUNK*N_) + c*N_ + n] = carry;
        carry = fmaf(a64, carry, v[c]);
    }
}

// ---------------------------------------------------------------------------
// K3: recombine carries, y = h @ Cm^T + x*Dv, clip, fused LayerNorm, store.
// 512 thr = 16 warps, warp owns 4 rows. x loads hoisted above all barriers.
// ---------------------------------------------------------------------------
__global__ void __launch_bounds__(512) k3(const float* __restrict__ x,
                                          const float* __restrict__ A,
                                          const float* __restrict__ Cm,
                                          const float* __restrict__ Dv,
                                          const float* __restrict__ gamma,
                                          const float* __restrict__ beta,
                                          float* __restrict__ out){
    __shared__ float sC[D_*17];       // [d][n] pad 17
    __shared__ float sh[N_*68];       // [n][t] pad 68
    __shared__ float sDv[D_], sg[D_], sb[D_];
    const int chunk = blockIdx.x, b = blockIdx.y;
    const int tid = threadIdx.x;
    const int warp = tid >> 5, lane = tid & 31;
    const int t0 = warp * 4;

    // hoisted x prefetch (independent of smem; overlaps staging latency)
    const float* xr = x + (size_t)(b*S_ + chunk*CHUNK + t0)*D_;
    float xv[4][8];
    #pragma unroll
    for (int r = 0; r < 4; r++)
        #pragma unroll
        for (int j = 0; j < 8; j++)
            xv[r][j] = xr[r*D_ + lane + 32*j];

    for (int i = tid; i < D_*N_; i += 512)
        sC[(i>>4)*17 + (i&15)] = Cm[i];
    for (int i = tid; i < D_; i += 512){ sDv[i]=Dv[i]; sg[i]=gamma[i]; sb[i]=beta[i]; }
    {
        const float* Hg = g_H + (size_t)(b*S_ + chunk*CHUNK)*N_;
        #pragma unroll
        for (int j = 0; j < 2; j++){
            int i = tid + j*512;
            int t = i >> 4, n = i & 15;
            sh[n*68 + t] = Hg[i];
        }
    }
    __syncthreads();

    // carry fixup: 64 threads, 16-step segments
    if (tid < 64){
        int n = tid & 15, seg = tid >> 4;
        float absA = fabsf(A[n]);
        float a = expf(-DTc*absA);
        float p = g_carry[b*(NCHUNK*N_) + chunk*N_ + n] * expf(-DTc*absA*(float)(seg*16));
        float* row = sh + n*68 + seg*16;
        #pragma unroll
        for (int tl = 0; tl < 16; tl++){
            p *= a;
            row[tl] += p;
        }
    }
    __syncthreads();

    float y[4][8];
    #pragma unroll
    for (int r = 0; r < 4; r++)
        #pragma unroll
        for (int j = 0; j < 8; j++)
            y[r][j] = xv[r][j] * sDv[lane + 32*j];

    #pragma unroll
    for (int n = 0; n < 16; n++){
        float4 h4 = *(const float4*)(sh + n*68 + t0);   // broadcast
        #pragma unroll
        for (int j = 0; j < 8; j++){
            float c = sC[(lane + 32*j)*17 + n];
            y[0][j] = fmaf(h4.x, c, y[0][j]);
            y[1][j] = fmaf(h4.y, c, y[1][j]);
            y[2][j] = fmaf(h4.z, c, y[2][j]);
            y[3][j] = fmaf(h4.w, c, y[3][j]);
        }
    }

    float* og = out + (size_t)(b*S_ + chunk*CHUNK + t0)*D_;
    #pragma unroll
    for (int r = 0; r < 4; r++){
        float s = 0.f, s2 = 0.f;
        #pragma unroll
        for (int j = 0; j < 8; j++){
            float v = fminf(fmaxf(y[r][j], -10.f), 10.f);
            y[r][j] = v;
            s += v;
            s2 = fmaf(v, v, s2);
        }
        #pragma unroll
        for (int o = 16; o; o >>= 1){
            s  += __shfl_xor_sync(0xffffffffu, s,  o);
            s2 += __shfl_xor_sync(0xffffffffu, s2, o);
        }
        float mu   = s * (1.f/256.f);
        float var  = fmaf(s2, 1.f/256.f, -mu*mu);
        float rinv = rsqrtf(var + LN_EPS);
        #pragma unroll
        for (int j = 0; j < 8; j++){
            int d = lane + 32*j;
            og[r*D_ + d] = fmaf((y[r][j]-mu)*rinv, sg[d], sb[d]);
        }
    }
}

// ---------------------------------------------------------------------------
extern "C" void kernel_launch(void* const* d_in, const int* in_sizes, int n_in,
                              void* d_out, int out_size){
    const float* x     = (const float*)d_in[0];
    const float* A     = (const float*)d_in[1];
    const float* Bm    = (const float*)d_in[2];
    const float* Cm    = (const float*)d_in[3];
    const float* Dv    = (const float*)d_in[4];
    const float* gamma = (const float*)d_in[5];
    const float* beta  = (const float*)d_in[6];
    float* out = (float*)d_out;

    size_t smem1 = (size_t)(2*256*PADX + 4096 + 256*20) * sizeof(float); // 110592 B
    cudaFuncSetAttribute(k1, cudaFuncAttributeMaxDynamicSharedMemorySize, (int)smem1);

    dim3 grid1(S_/256, B_);     // 16 x 16 = 256 blocks
    dim3 grid3(NCHUNK, B_);     // 64 x 16
    k1<<<grid1, 256, smem1>>>(x, A, Bm);
    k2<<<1, 256>>>(A);
    k3<<<grid3, 512>>>(x, A, Cm, Dv, gamma, beta, out);
}

// round 6
// speedup vs baseline: 1.7261x; 1.0247x over previous
#include <cuda_runtime.h>
#include <math.h>

#define DTc 1e-4f
#define LN_EPS 1e-5f
#define B_ 16
#define S_ 4096
#define D_ 256
#define N_ 16
#define CHUNK 64
#define NCHUNK (S_/CHUNK)   // 64
#define PADX 36             // 32 k-cols + 4 pad

// scratch (no cudaMalloc allowed)
__device__ float g_H[B_*S_*N_];          // 4 MB

typedef unsigned long long ull;

__device__ __forceinline__ void fma2(ull& d, ull a, ull b){
    asm("fma.rn.f32x2 %0, %1, %2, %0;" : "+l"(d) : "l"(a), "l"(b));
}
__device__ __forceinline__ ull mul2(ull a, ull b){
    ull r;
    asm("mul.rn.f32x2 %0, %1, %2;" : "=l"(r) : "l"(a), "l"(b));
    return r;
}
__device__ __forceinline__ ull pack2(float v){
    ull r;
    asm("mov.b64 %0, {%1, %1};" : "=l"(r) : "f"(v));
    return r;
}
__device__ __forceinline__ void unpk(float& lo, float& hi, ull v){
    asm("mov.b64 {%0, %1}, %2;" : "=f"(lo), "=f"(hi) : "l"(v));
}
__device__ __forceinline__ void cpa16(float* s, const float4* g){
    unsigned sa = (unsigned)__cvta_generic_to_shared(s);
    asm volatile("cp.async.ca.shared.global [%0], [%1], 16;" :: "r"(sa), "l"(g));
}

// ---------------------------------------------------------------------------
// K1: U = DT * x @ Bm^T for 256 rows (4 chunks). 256 thr; thread computes
// rows {tt,tt+64,tt+128,tt+192} x n in {nt,nt+4,nt+8,nt+12}. FFMA2 over
// k-parity pairs (acc = (even,odd) partials), cp.async double-buffered
// 32-col k-tiles, then per-chunk local scans (h0=0).
// ---------------------------------------------------------------------------
__global__ void __launch_bounds__(256,2) k1(const float* __restrict__ x,
                                            const float* __restrict__ A,
                                            const float* __restrict__ Bm){
    extern __shared__ float sm[];
    float* sx0 = sm;                       // 256*36
    float* sx1 = sm + 256*PADX;            // 256*36
    float* sw2 = sm + 2*256*PADX;          // [n][k] pad 260: 16*260
    float* su  = sw2 + 16*260;             // [row][n] pad 20: 256*20
    const int blk = blockIdx.x, b = blockIdx.y;
    const int tid = threadIdx.x;
    const int nt = tid & 3, tt = tid >> 2; // tt 0..63

    // stage W: sw2[n][k] = DT * Bm[n][k]  (k-contiguous for f32x2 pairs)
    for (int i = tid; i < N_*D_; i += 256){
        int nn = i >> 8, k = i & 255;
        sw2[nn*260 + k] = DTc * Bm[i];
    }

    const float4* xg = (const float4*)(x + (size_t)(b*S_ + blk*256)*D_);

    ull acc[4][4];                         // [row r][n-slot i], lo=even-k hi=odd-k
    #pragma unroll
    for (int r = 0; r < 4; r++)
        #pragma unroll
        for (int i = 0; i < 4; i++) acc[r][i] = 0ull;

    // preload tile 0
    #pragma unroll
    for (int j = 0; j < 8; j++){
        int i = tid + j*256;
        int t = i >> 3, q = i & 7;
        cpa16(sx0 + t*PADX + q*4, xg + (size_t)t*64 + q);
    }
    asm volatile("cp.async.commit_group;");

    #pragma unroll
    for (int kt = 0; kt < 8; kt++){
        float* cur = (kt & 1) ? sx1 : sx0;
        float* nxt = (kt & 1) ? sx0 : sx1;
        if (kt < 7){
            #pragma unroll
            for (int j = 0; j < 8; j++){
                int i = tid + j*256;
                int t = i >> 3, q = i & 7;
                cpa16(nxt + t*PADX + q*4, xg + (size_t)t*64 + (kt+1)*8 + q);
            }
            asm volatile("cp.async.commit_group;");
            asm volatile("cp.async.wait_group 1;");
        } else {
            asm volatile("cp.async.wait_group 0;");
        }
        __syncthreads();

        const ulonglong2* xr0 = (const ulonglong2*)(cur + (tt      )*PADX);
        const ulonglong2* xr1 = (const ulonglong2*)(cur + (tt +  64)*PADX);
        const ulonglong2* xr2 = (const ulonglong2*)(cur + (tt + 128)*PADX);
        const ulonglong2* xr3 = (const ulonglong2*)(cur + (tt + 192)*PADX);
        const ulonglong2* wr0 = (const ulonglong2*)(sw2 + (nt     )*260 + kt*32);
        const ulonglong2* wr1 = (const ulonglong2*)(sw2 + (nt +  4)*260 + kt*32);
        const ulonglong2* wr2 = (const ulonglong2*)(sw2 + (nt +  8)*260 + kt*32);
        const ulonglong2* wr3 = (const ulonglong2*)(sw2 + (nt + 12)*260 + kt*32);

        #pragma unroll
        for (int k4 = 0; k4 < 8; k4++){
            ulonglong2 xa = xr0[k4], xb = xr1[k4], xc = xr2[k4], xd = xr3[k4];
            ulonglong2 w0 = wr0[k4], w1 = wr1[k4], w2 = wr2[k4], w3 = wr3[k4];
            fma2(acc[0][0], xa.x, w0.x); fma2(acc[0][0], xa.y, w0.y);
            fma2(acc[0][1], xa.x, w1.x); fma2(acc[0][1], xa.y, w1.y);
            fma2(acc[0][2], xa.x, w2.x); fma2(acc[0][2], xa.y, w2.y);
            fma2(acc[0][3], xa.x, w3.x); fma2(acc[0][3], xa.y, w3.y);
            fma2(acc[1][0], xb.x, w0.x); fma2(acc[1][0], xb.y, w0.y);
            fma2(acc[1][1], xb.x, w1.x); fma2(acc[1][1], xb.y, w1.y);
            fma2(acc[1][2], xb.x, w2.x); fma2(acc[1][2], xb.y, w2.y);
            fma2(acc[1][3], xb.x, w3.x); fma2(acc[1][3], xb.y, w3.y);
            fma2(acc[2][0], xc.x, w0.x); fma2(acc[2][0], xc.y, w0.y);
            fma2(acc[2][1], xc.x, w1.x); fma2(acc[2][1], xc.y, w1.y);
            fma2(acc[2][2], xc.x, w2.x); fma2(acc[2][2], xc.y, w2.y);
            fma2(acc[2][3], xc.x, w3.x); fma2(acc[2][3], xc.y, w3.y);
            fma2(acc[3][0], xd.x, w0.x); fma2(acc[3][0], xd.y, w0.y);
            fma2(acc[3][1], xd.x, w1.x); fma2(acc[3][1], xd.y, w1.y);
            fma2(acc[3][2], xd.x, w2.x); fma2(acc[3][2], xd.y, w2.y);
            fma2(acc[3][3], xd.x, w3.x); fma2(acc[3][3], xd.y, w3.y);
        }
        __syncthreads();
    }

    #pragma unroll
    for (int r = 0; r < 4; r++)
        #pragma unroll
        for (int i = 0; i < 4; i++){
            float lo, hi;
            unpk(lo, hi, acc[r][i]);
            su[(tt + 64*r)*20 + (nt + 4*i)] = lo + hi;
        }
    __syncthreads();

    // local scans: 64 chains (4 chunks x 16 n), h0 = 0
    if (tid < 64){
        int n = tid & 15, cc = tid >> 4;
        float a = expf(-DTc*fabsf(A[n]));
        float h = 0.f;
        float* p = su + cc*64*20 + n;
        #pragma unroll 8
        for (int t = 0; t < CHUNK; t++){
            h = fmaf(a, h, p[t*20]);
            p[t*20] = h;
        }
    }
    __syncthreads();

    float* Hg = g_H + (size_t)(b*S_ + blk*256)*N_;
    #pragma unroll
    for (int j = 0; j < 16; j++){
        int i = tid + j*256;              // 4096 elems
        Hg[i] = su[(i>>4)*20 + (i&15)];
    }
}

// ---------------------------------------------------------------------------
// K3: self-computed carry, recombine, y = h @ Cm^T + x*Dv, clip, LayerNorm.
// 512 thr = 16 warps; warp owns 4 rows, lane owns d = 4*lane + 128*j.
// FFMA2 GEMM, vector LDG/STG. No k2 kernel.
// ---------------------------------------------------------------------------
__global__ void __launch_bounds__(512) k3(const float* __restrict__ x,
                                          const float* __restrict__ A,
                                          const float* __restrict__ Cm,
                                          const float* __restrict__ Dv,
                                          const float* __restrict__ gamma,
                                          const float* __restrict__ beta,
                                          float* __restrict__ out){
    __shared__ float sC[N_*260];      // [n][d] pad 260 (16B-aligned rows)
    __shared__ float sh[N_*68];       // [n][t] pad 68
    __shared__ float sDv[D_], sg[D_], sb[D_];
    __shared__ float scarr[N_];
    const int chunk = blockIdx.x, b = blockIdx.y;
    const int tid = threadIdx.x;
    const int warp = tid >> 5, lane = tid & 31;
    const int t0 = warp * 4;

    // hoisted x prefetch: 8 LDG.128 per thread
    const float* xr = x + (size_t)(b*S_ + chunk*CHUNK + t0)*D_;
    float4 xv[4][2];
    #pragma unroll
    for (int r = 0; r < 4; r++)
        #pragma unroll
        for (int j = 0; j < 2; j++)
            xv[r][j] = *(const float4*)(xr + r*D_ + 4*lane + 128*j);

    // carry recurrence for this chunk (threads 0..15), overlapped with staging
    if (tid < 16){
        const int n = tid;
        float a = expf(-DTc*fabsf(A[n]));
        float a2=a*a, a4=a2*a2, a8=a4*a4, a16=a8*a8, a32=a16*a16, a64=a32*a32;
        float carry = 0.f;
        for (int c0 = 0; c0 < chunk; c0 += 16){
            float v[16];
            #pragma unroll
            for (int i = 0; i < 16; i++)
                if (c0 + i < chunk)
                    v[i] = g_H[((size_t)b*S_ + (c0+i)*CHUNK + (CHUNK-1))*N_ + n];
            #pragma unroll
            for (int i = 0; i < 16; i++)
                if (c0 + i < chunk)
                    carry = fmaf(a64, carry, v[i]);
        }
        scarr[n] = carry;
    }

    for (int i = tid; i < D_*N_; i += 512){
        int d = i >> 4, n = i & 15;
        sC[n*260 + d] = Cm[i];        // Cm[d][n]
    }
    for (int i = tid; i < D_; i += 512){ sDv[i]=Dv[i]; sg[i]=gamma[i]; sb[i]=beta[i]; }
    {
        const float* Hg = g_H + (size_t)(b*S_ + chunk*CHUNK)*N_;
        #pragma unroll
        for (int j = 0; j < 2; j++){
            int i = tid + j*512;
            int t = i >> 4, n = i & 15;
            sh[n*68 + t] = Hg[i];
        }
    }
    __syncthreads();

    // carry fixup: 64 threads, 16-step segments: sh[n][t] += a^{t+1}*carry
    if (tid < 64){
        int n = tid & 15, seg = tid >> 4;
        float absA = fabsf(A[n]);
        float a = expf(-DTc*absA);
        float p = scarr[n] * expf(-DTc*absA*(float)(seg*16));
        float* row = sh + n*68 + seg*16;
        #pragma unroll
        for (int tl = 0; tl < 16; tl++){
            p *= a;
            row[tl] += p;
        }
    }
    __syncthreads();

    // y = x*Dv (f32x2)
    ull y2[4][2][2];
    #pragma unroll
    for (int r = 0; r < 4; r++)
        #pragma unroll
        for (int j = 0; j < 2; j++){
            int d = 4*lane + 128*j;
            ulonglong2 xp = *(ulonglong2*)&xv[r][j];
            ulonglong2 dv = *(const ulonglong2*)(sDv + d);
            y2[r][j][0] = mul2(xp.x, dv.x);
            y2[r][j][1] = mul2(xp.y, dv.y);
        }

    // GEMM: 16 n, FFMA2
    #pragma unroll
    for (int n = 0; n < 16; n++){
        float4 h4 = *(const float4*)(sh + n*68 + t0);   // broadcast
        ull ha = pack2(h4.x), hb = pack2(h4.y), hc = pack2(h4.z), hd = pack2(h4.w);
        #pragma unroll
        for (int j = 0; j < 2; j++){
            ulonglong2 c2 = *(const ulonglong2*)(sC + n*260 + 4*lane + 128*j);
            fma2(y2[0][j][0], ha, c2.x); fma2(y2[0][j][1], ha, c2.y);
            fma2(y2[1][j][0], hb, c2.x); fma2(y2[1][j][1], hb, c2.y);
            fma2(y2[2][j][0], hc, c2.x); fma2(y2[2][j][1], hc, c2.y);
            fma2(y2[3][j][0], hd, c2.x); fma2(y2[3][j][1], hd, c2.y);
        }
    }

    float* og = out + (size_t)(b*S_ + chunk*CHUNK + t0)*D_;
    #pragma unroll
    for (int r = 0; r < 4; r++){
        float yv[8];
        float s = 0.f, s2 = 0.f;
        #pragma unroll
        for (int j = 0; j < 2; j++)
            #pragma unroll
            for (int p2 = 0; p2 < 2; p2++){
                float lo, hi;
                unpk(lo, hi, y2[r][j][p2]);
                lo = fminf(fmaxf(lo, -10.f), 10.f);
                hi = fminf(fmaxf(hi, -10.f), 10.f);
                yv[j*4 + p2*2]     = lo;
                yv[j*4 + p2*2 + 1] = hi;
                s += lo + hi;
                s2 = fmaf(lo, lo, s2);
                s2 = fmaf(hi, hi, s2);
            }
        #pragma unroll
        for (int o = 16; o; o >>= 1){
            s  += __shfl_xor_sync(0xffffffffu, s,  o);
            s2 += __shfl_xor_sync(0xffffffffu, s2, o);
        }
        float mu   = s * (1.f/256.f);
        float var  = fmaf(s2, 1.f/256.f, -mu*mu);
        float rinv = rsqrtf(var + LN_EPS);
        #pragma unroll
        for (int j = 0; j < 2; j++){
            int d = 4*lane + 128*j;
            float4 gg = *(const float4*)(sg + d);
            float4 bb = *(const float4*)(sb + d);
            float4 o4;
            o4.x = fmaf((yv[j*4+0]-mu)*rinv, gg.x, bb.x);
            o4.y = fmaf((yv[j*4+1]-mu)*rinv, gg.y, bb.y);
            o4.z = fmaf((yv[j*4+2]-mu)*rinv, gg.z, bb.z);
            o4.w = fmaf((yv[j*4+3]-mu)*rinv, gg.w, bb.w);
            *(float4*)(og + r*D_ + d) = o4;
        }
    }
}

// ---------------------------------------------------------------------------
extern "C" void kernel_launch(void* const* d_in, const int* in_sizes, int n_in,
                              void* d_out, int out_size){
    const float* x     = (const float*)d_in[0];
    const float* A     = (const float*)d_in[1];
    const float* Bm    = (const float*)d_in[2];
    const float* Cm    = (const float*)d_in[3];
    const float* Dv    = (const float*)d_in[4];
    const float* gamma = (const float*)d_in[5];
    const float* beta  = (const float*)d_in[6];
    float* out = (float*)d_out;

    size_t smem1 = (size_t)(2*256*PADX + 16*260 + 256*20) * sizeof(float); // 110848 B
    cudaFuncSetAttribute(k1, cudaFuncAttributeMaxDynamicSharedMemorySize, (int)smem1);

    dim3 grid1(S_/256, B_);     // 16 x 16 = 256 blocks
    dim3 grid3(NCHUNK, B_);     // 64 x 16 = 1024 blocks
    k1<<<grid1, 256, smem1>>>(x, A, Bm);
    k3<<<grid3, 512>>>(x, A, Cm, Dv, gamma, beta, out);
}